// round 8
// baseline (speedup 1.0000x reference)
#include <cuda_runtime.h>
#include <cstdint>

#define N_NODES 50000
#define N_EDGES 600000
#define D_K     128
#define D_H1    128
#define D_H2    64

// ---------------- scratch (device globals: no allocation allowed) ----------
// g_deg is zero at module load and re-zeroed by k_scan each run (invariant).
__device__ int   g_deg     [N_NODES];
__device__ float g_dinv    [N_NODES];
__device__ int   g_rowstart[N_NODES + 1];
__device__ int   g_cursor  [N_NODES];
__device__ int   g_csr_src [N_EDGES];
__device__ __align__(16) float g_t1  [N_NODES * D_H1];   // (x @ W1) * dinv[row]
__device__ __align__(16) float g_agg1[N_NODES * D_H1];   // aggregated layer-1
__device__ __align__(16) float g_t2  [N_NODES * D_H2];   // (relu(agg1+b1) @ W2) * dinv[row]

__device__ __forceinline__ int clampi(int v) {
    return min(max(v, 0), N_NODES - 1);
}

// ---------------- degree count (into zeroed g_deg) --------------------------
__global__ void k_count_deg(const int* __restrict__ ei) {
    int e = blockIdx.x * blockDim.x + threadIdx.x;
    if (e < N_EDGES) atomicAdd(&g_deg[clampi(ei[N_EDGES + e])], 1);  // dst
}

// ---------------- single-block scan: rowstart/cursor/dinv, re-zero deg ------
// incoming[n] = deg[n]; self-loop accounted as dinv = rsqrt(deg+1).
__global__ void __launch_bounds__(1024) k_scan() {
    __shared__ int s[1024];
    const int T = 1024;
    const int C = (N_NODES + T - 1) / T;    // 49
    int t = threadIdx.x;
    int base = t * C;

    int sum = 0;
    for (int i = 0; i < C; i++) {
        int n = base + i;
        if (n < N_NODES) sum += g_deg[n];
    }
    s[t] = sum;
    __syncthreads();
    for (int off = 1; off < T; off <<= 1) {
        int add = (t >= off) ? s[t - off] : 0;
        __syncthreads();
        s[t] += add;
        __syncthreads();
    }
    int run = s[t] - sum;                   // exclusive prefix
    for (int i = 0; i < C; i++) {
        int n = base + i;
        if (n < N_NODES) {
            int d = g_deg[n];
            g_rowstart[n] = run;
            g_cursor[n]   = run;
            g_dinv[n]     = rsqrtf((float)(d + 1));
            g_deg[n]      = 0;              // restore zero for next run
            run += d;
        }
    }
    if (t == T - 1) g_rowstart[N_NODES] = run;   // == N_EDGES
}

// ---------------- CSR fill (src only) ---------------------------------------
__global__ void k_fill(const int* __restrict__ ei) {
    int e = blockIdx.x * blockDim.x + threadIdx.x;
    if (e >= N_EDGES) return;
    int src = clampi(ei[e]);
    int dst = clampi(ei[N_EDGES + e]);
    int pos = atomicAdd(&g_cursor[dst], 1);
    g_csr_src[pos] = src;
}

// ---------------- 8x8-tile SGEMM: T = (f(A) @ W) * dinv[row] ----------------
template<int BM, int BN, bool IN_TRANS>
__device__ __forceinline__ void gemm8x8_body(const float* __restrict__ A,
                                             const float* __restrict__ W,
                                             const float* __restrict__ b_in,
                                             float* __restrict__ T)
{
    constexpr int KC      = 32;
    constexpr int THREADS = (BM / 8) * (BN / 8);
    constexpr int TX      = BN / 8;          // col groups
    __shared__ float As[KC][BM];              // transposed A chunk
    __shared__ float Ws[KC][BN];

    const int tid  = threadIdx.x;
    const int tx   = tid % TX;
    const int ty   = tid / TX;
    const int row0 = blockIdx.x * BM;

    float acc[8][8];
#pragma unroll
    for (int i = 0; i < 8; i++)
#pragma unroll
        for (int j = 0; j < 8; j++) acc[i][j] = 0.f;

    for (int kc = 0; kc < D_K; kc += KC) {
        constexpr int AF4 = BM * KC / 4;      // float4 slots
#pragma unroll
        for (int q = 0; q < AF4 / THREADS; q++) {
            int f  = tid + q * THREADS;
            int r  = f >> 3;
            int k4 = f & 7;
            float4 v = make_float4(0.f, 0.f, 0.f, 0.f);
            int grow = row0 + r;
            if (grow < N_NODES)
                v = *(const float4*)&A[(size_t)grow * D_K + kc + k4 * 4];
            if constexpr (IN_TRANS) {
                float4 bb = *(const float4*)&b_in[kc + k4 * 4];
                v.x = fmaxf(v.x + bb.x, 0.f);
                v.y = fmaxf(v.y + bb.y, 0.f);
                v.z = fmaxf(v.z + bb.z, 0.f);
                v.w = fmaxf(v.w + bb.w, 0.f);
            }
            As[k4 * 4 + 0][r] = v.x;
            As[k4 * 4 + 1][r] = v.y;
            As[k4 * 4 + 2][r] = v.z;
            As[k4 * 4 + 3][r] = v.w;
        }
        {
            const float4* Wg  = (const float4*)&W[(size_t)kc * BN];
            float4*       Wsp = (float4*)&Ws[0][0];
            constexpr int WF4 = KC * BN / 4;
#pragma unroll
            for (int q = 0; q < WF4 / THREADS; q++)
                Wsp[tid + q * THREADS] = Wg[tid + q * THREADS];
        }
        __syncthreads();

#pragma unroll
        for (int k = 0; k < KC; k++) {
            const float4* Ar = (const float4*)&As[k][0];
            const float4* Wr = (const float4*)&Ws[k][0];
            float4 a0 = Ar[ty * 2 + 0];
            float4 a1 = Ar[ty * 2 + 1];
            float4 w0 = Wr[tx * 2 + 0];
            float4 w1 = Wr[tx * 2 + 1];
            float av[8] = {a0.x, a0.y, a0.z, a0.w, a1.x, a1.y, a1.z, a1.w};
            float wv[8] = {w0.x, w0.y, w0.z, w0.w, w1.x, w1.y, w1.z, w1.w};
#pragma unroll
            for (int i = 0; i < 8; i++)
#pragma unroll
                for (int j = 0; j < 8; j++)
                    acc[i][j] = fmaf(av[i], wv[j], acc[i][j]);
        }
        __syncthreads();
    }

#pragma unroll
    for (int i = 0; i < 8; i++) {
        int r = row0 + ty * 8 + i;
        if (r >= N_NODES) continue;
        float dv = g_dinv[r];
        float4 t0 = make_float4(acc[i][0] * dv, acc[i][1] * dv,
                                acc[i][2] * dv, acc[i][3] * dv);
        float4 t1 = make_float4(acc[i][4] * dv, acc[i][5] * dv,
                                acc[i][6] * dv, acc[i][7] * dv);
        *(float4*)&T[(size_t)r * BN + tx * 8 + 0] = t0;
        *(float4*)&T[(size_t)r * BN + tx * 8 + 4] = t1;
    }
}

__global__ void __launch_bounds__(256)
k_gemm1(const float* __restrict__ x, const float* __restrict__ W1) {
    gemm8x8_body<128, 128, false>(x, W1, nullptr, g_t1);
}

__global__ void __launch_bounds__(128)
k_gemm2(const float* __restrict__ W2, const float* __restrict__ b1) {
    gemm8x8_body<128, 64, true>(g_agg1, W2, b1, g_t2);
}

// ---------------- layer-1 aggregate: gather, warp per node, MLP=4 -----------
__global__ void k_agg1() {
    int n    = (blockIdx.x * blockDim.x + threadIdx.x) >> 5;
    int lane = threadIdx.x & 31;
    if (n >= N_NODES) return;

    int   s0 = g_rowstart[n];
    int   s1 = g_rowstart[n + 1];
    float dv = g_dinv[n];

    float4 acc = *(const float4*)&g_t1[(size_t)n * D_H1 + lane * 4];

    int e = s0;
    for (; e + 3 < s1; e += 4) {
        int sA = g_csr_src[e];
        int sB = g_csr_src[e + 1];
        int sC = g_csr_src[e + 2];
        int sD = g_csr_src[e + 3];
        float4 vA = *(const float4*)&g_t1[(size_t)sA * D_H1 + lane * 4];
        float4 vB = *(const float4*)&g_t1[(size_t)sB * D_H1 + lane * 4];
        float4 vC = *(const float4*)&g_t1[(size_t)sC * D_H1 + lane * 4];
        float4 vD = *(const float4*)&g_t1[(size_t)sD * D_H1 + lane * 4];
        acc.x += (vA.x + vB.x) + (vC.x + vD.x);
        acc.y += (vA.y + vB.y) + (vC.y + vD.y);
        acc.z += (vA.z + vB.z) + (vC.z + vD.z);
        acc.w += (vA.w + vB.w) + (vC.w + vD.w);
    }
    for (; e < s1; e++) {
        int src = g_csr_src[e];
        float4 v = *(const float4*)&g_t1[(size_t)src * D_H1 + lane * 4];
        acc.x += v.x; acc.y += v.y; acc.z += v.z; acc.w += v.w;
    }
    acc.x *= dv; acc.y *= dv; acc.z *= dv; acc.w *= dv;
    *(float4*)&g_agg1[(size_t)n * D_H1 + lane * 4] = acc;
}

// ---------------- layer-2 aggregate fused with final GEMV, MLP=4 ------------
__global__ void k_agg2_final(const float* __restrict__ b2,
                             const float* __restrict__ W3,
                             const float* __restrict__ b3,
                             float* __restrict__ out)
{
    int n    = (blockIdx.x * blockDim.x + threadIdx.x) >> 5;
    int lane = threadIdx.x & 31;
    if (n >= N_NODES) return;

    int   s0 = g_rowstart[n];
    int   s1 = g_rowstart[n + 1];
    float dv = g_dinv[n];

    float2 acc = *(const float2*)&g_t2[(size_t)n * D_H2 + lane * 2];

    int e = s0;
    for (; e + 3 < s1; e += 4) {
        int sA = g_csr_src[e];
        int sB = g_csr_src[e + 1];
        int sC = g_csr_src[e + 2];
        int sD = g_csr_src[e + 3];
        float2 vA = *(const float2*)&g_t2[(size_t)sA * D_H2 + lane * 2];
        float2 vB = *(const float2*)&g_t2[(size_t)sB * D_H2 + lane * 2];
        float2 vC = *(const float2*)&g_t2[(size_t)sC * D_H2 + lane * 2];
        float2 vD = *(const float2*)&g_t2[(size_t)sD * D_H2 + lane * 2];
        acc.x += (vA.x + vB.x) + (vC.x + vD.x);
        acc.y += (vA.y + vB.y) + (vC.y + vD.y);
    }
    for (; e < s1; e++) {
        int src = g_csr_src[e];
        float2 v = *(const float2*)&g_t2[(size_t)src * D_H2 + lane * 2];
        acc.x += v.x; acc.y += v.y;
    }
    acc.x *= dv; acc.y *= dv;

    float2 bb = *(const float2*)&b2[lane * 2];
    float2 w  = *(const float2*)&W3[lane * 2];
    float h0 = fmaxf(acc.x + bb.x, 0.f);
    float h1 = fmaxf(acc.y + bb.y, 0.f);
    float s  = fmaf(h0, w.x, h1 * w.y);
#pragma unroll
    for (int o = 16; o; o >>= 1) s += __shfl_xor_sync(0xffffffffu, s, o);
    if (lane == 0) out[n] = s + b3[0];
}

// ---------------- launch (single stream) ------------------------------------
// Order puts gemm1 at launch slot #4 so the ncu capture (which has landed on
// slot #4 every round) profiles the GEMM next time.
extern "C" void kernel_launch(void* const* d_in, const int* in_sizes, int n_in,
                              void* d_out, int out_size)
{
    const float* x  = (const float*)d_in[0];
    const int*   ei = (const int*)d_in[1];     // int32 edge_index
    const float* W1 = (const float*)d_in[2];
    const float* b1 = (const float*)d_in[3];
    const float* W2 = (const float*)d_in[4];
    const float* b2 = (const float*)d_in[5];
    const float* W3 = (const float*)d_in[6];
    const float* b3 = (const float*)d_in[7];
    float*       out = (float*)d_out;
    (void)in_sizes; (void)n_in; (void)out_size;

    k_count_deg<<<(N_EDGES + 255) / 256, 256>>>(ei);
    k_scan     <<<1, 1024>>>();
    k_fill     <<<(N_EDGES + 255) / 256, 256>>>(ei);

    k_gemm1<<<(N_NODES + 127) / 128, 256>>>(x, W1);        // slot #4
    k_agg1 <<<(N_NODES * 32 + 255) / 256, 256>>>();

    k_gemm2<<<(N_NODES + 127) / 128, 128>>>(W2, b1);
    k_agg2_final<<<(N_NODES * 32 + 255) / 256, 256>>>(b2, W3, b3, out);
}

// round 9
// speedup vs baseline: 1.0842x; 1.0842x over previous
#include <cuda_runtime.h>
#include <cstdint>

#define N_NODES 50000
#define N_EDGES 600000
#define D_K     128
#define D_H1    128
#define D_H2    64

// ---------------- scratch (device globals: no allocation allowed) ----------
// g_deg is zero at module load and re-zeroed by k_scan each run (invariant).
__device__ int   g_deg     [N_NODES];
__device__ float g_dinv    [N_NODES];
__device__ int   g_rowstart[N_NODES + 1];
__device__ int   g_cursor  [N_NODES];
__device__ int   g_csr_src [N_EDGES];
__device__ __align__(16) float g_t1  [N_NODES * D_H1];   // (x @ W1) * dinv[row]
__device__ __align__(16) float g_agg1[N_NODES * D_H1];   // aggregated layer-1
__device__ __align__(16) float g_t2  [N_NODES * D_H2];   // (relu(agg1+b1) @ W2) * dinv[row]

__device__ __forceinline__ int clampi(int v) {
    return min(max(v, 0), N_NODES - 1);
}

// ---------------- degree count (into zeroed g_deg) --------------------------
__global__ void k_count_deg(const int* __restrict__ ei) {
    int e = blockIdx.x * blockDim.x + threadIdx.x;
    if (e < N_EDGES) atomicAdd(&g_deg[clampi(ei[N_EDGES + e])], 1);  // dst
}

// ---------------- single-block scan: rowstart/cursor/dinv, re-zero deg ------
__global__ void __launch_bounds__(1024) k_scan() {
    __shared__ int s[1024];
    const int T = 1024;
    const int C = (N_NODES + T - 1) / T;    // 49
    int t = threadIdx.x;
    int base = t * C;

    int sum = 0;
    for (int i = 0; i < C; i++) {
        int n = base + i;
        if (n < N_NODES) sum += g_deg[n];
    }
    s[t] = sum;
    __syncthreads();
    for (int off = 1; off < T; off <<= 1) {
        int add = (t >= off) ? s[t - off] : 0;
        __syncthreads();
        s[t] += add;
        __syncthreads();
    }
    int run = s[t] - sum;                   // exclusive prefix
    for (int i = 0; i < C; i++) {
        int n = base + i;
        if (n < N_NODES) {
            int d = g_deg[n];
            g_rowstart[n] = run;
            g_cursor[n]   = run;
            g_dinv[n]     = rsqrtf((float)(d + 1));  // +1 self-loop
            g_deg[n]      = 0;              // restore zero for next run
            run += d;
        }
    }
    if (t == T - 1) g_rowstart[N_NODES] = run;   // == N_EDGES
}

// ---------------- CSR fill (src only) ---------------------------------------
__global__ void k_fill(const int* __restrict__ ei) {
    int e = blockIdx.x * blockDim.x + threadIdx.x;
    if (e >= N_EDGES) return;
    int src = clampi(ei[e]);
    int dst = clampi(ei[N_EDGES + e]);
    int pos = atomicAdd(&g_cursor[dst], 1);
    g_csr_src[pos] = src;
}

// ---------------- tensor-core GEMM (3xTF32): T = (f(A) @ W) * dinv[row] -----
__device__ __forceinline__ unsigned f2tf32(float x) {
    unsigned r;
    asm("cvt.rna.tf32.f32 %0, %1;" : "=r"(r) : "f"(x));
    return r;
}

__device__ __forceinline__ void mma_tf32(float* d, const unsigned* a, const unsigned* b) {
    asm volatile(
        "mma.sync.aligned.m16n8k8.row.col.f32.tf32.tf32.f32 "
        "{%0,%1,%2,%3}, {%4,%5,%6,%7}, {%8,%9}, {%0,%1,%2,%3};"
        : "+f"(d[0]), "+f"(d[1]), "+f"(d[2]), "+f"(d[3])
        : "r"(a[0]), "r"(a[1]), "r"(a[2]), "r"(a[3]), "r"(b[0]), "r"(b[1]));
}

// BM x BN block tile, WM x WN warps (8 warps = 256 threads).
// Warp tile (BM/WM) x (BN/WN); MT m16-tiles, NT n8-tiles per warp.
// 3xTF32: D += Ahi*Bhi + Ahi*Blo + Alo*Bhi  (error ~1e-6, fp32-class).
template<int BM, int BN, int WM, int WN, bool IN_TRANS>
__device__ __forceinline__ void gemm_tc_body(const float* __restrict__ A,
                                             const float* __restrict__ W,
                                             const float* __restrict__ b_in,
                                             float* __restrict__ T)
{
    constexpr int KC      = 32;
    constexpr int THREADS = WM * WN * 32;
    constexpr int MT      = BM / WM / 16;
    constexpr int NT      = BN / WN / 8;
    constexpr int AP      = KC + 4;          // A row pad
    constexpr int WP      = BN + 4;          // W row pad

    __shared__ float As[BM][AP];              // [m][k]
    __shared__ float Ws[KC][WP];              // [k][n]

    const int tid   = threadIdx.x;
    const int wid   = tid >> 5;
    const int lane  = tid & 31;
    const int wm    = wid % WM;
    const int wn    = wid / WM;
    const int group = lane >> 2;              // 0..7
    const int tig   = lane & 3;               // 0..3
    const int row0  = blockIdx.x * BM;
    const int mbase = wm * (BM / WM);
    const int nbase = wn * (BN / WN);

    float acc[MT][NT][4];
#pragma unroll
    for (int im = 0; im < MT; im++)
#pragma unroll
        for (int in = 0; in < NT; in++)
#pragma unroll
            for (int e = 0; e < 4; e++) acc[im][in][e] = 0.f;

    for (int kc = 0; kc < D_K; kc += KC) {
        // ---- stage A chunk (BM x 32), fused relu(+b) if IN_TRANS ----------
#pragma unroll
        for (int q = 0; q < BM * (KC / 4) / THREADS; q++) {
            int f  = tid + q * THREADS;
            int r  = f >> 3;                  // 8 float4 per row
            int k4 = f & 7;
            float4 v = make_float4(0.f, 0.f, 0.f, 0.f);
            int gr = row0 + r;
            if (gr < N_NODES)
                v = *(const float4*)&A[(size_t)gr * D_K + kc + k4 * 4];
            if constexpr (IN_TRANS) {
                float4 bb = *(const float4*)&b_in[kc + k4 * 4];
                v.x = fmaxf(v.x + bb.x, 0.f);
                v.y = fmaxf(v.y + bb.y, 0.f);
                v.z = fmaxf(v.z + bb.z, 0.f);
                v.w = fmaxf(v.w + bb.w, 0.f);
            }
            *(float4*)&As[r][k4 * 4] = v;
        }
        // ---- stage W chunk (32 x BN) ---------------------------------------
#pragma unroll
        for (int q = 0; q < KC * (BN / 4) / THREADS; q++) {
            int f  = tid + q * THREADS;
            int kk = f / (BN / 4);
            int n4 = f % (BN / 4);
            *(float4*)&Ws[kk][n4 * 4] =
                *(const float4*)&W[(size_t)(kc + kk) * BN + n4 * 4];
        }
        __syncthreads();

#pragma unroll
        for (int ks = 0; ks < KC / 8; ks++) {
            // A fragments + hi/lo split (PTX m16n8k8 row-major layout)
            unsigned ah[MT][4], al[MT][4];
#pragma unroll
            for (int im = 0; im < MT; im++) {
#pragma unroll
                for (int e = 0; e < 4; e++) {
                    int r = mbase + im * 16 + group + (e & 1) * 8;
                    int k = ks * 8 + tig + (e >> 1) * 4;
                    float a = As[r][k];
                    unsigned h = f2tf32(a);
                    ah[im][e] = h;
                    al[im][e] = f2tf32(a - __uint_as_float(h));
                }
            }
#pragma unroll
            for (int in = 0; in < NT; in++) {
                unsigned bh[2], bl[2];
#pragma unroll
                for (int e = 0; e < 2; e++) {
                    int k = ks * 8 + tig + e * 4;
                    int n = nbase + in * 8 + group;
                    float b = Ws[k][n];
                    unsigned h = f2tf32(b);
                    bh[e] = h;
                    bl[e] = f2tf32(b - __uint_as_float(h));
                }
#pragma unroll
                for (int im = 0; im < MT; im++) {
                    mma_tf32(acc[im][in], ah[im], bh);
                    mma_tf32(acc[im][in], ah[im], bl);
                    mma_tf32(acc[im][in], al[im], bh);
                }
            }
        }
        __syncthreads();
    }

    // ---- epilogue: prescale by dinv[row], store (c-fragment layout) -------
#pragma unroll
    for (int im = 0; im < MT; im++) {
#pragma unroll
        for (int half = 0; half < 2; half++) {
            int r = row0 + mbase + im * 16 + group + half * 8;
            if (r >= N_NODES) continue;
            float dv = g_dinv[r];
#pragma unroll
            for (int in = 0; in < NT; in++) {
                float2 t;
                t.x = acc[im][in][half * 2 + 0] * dv;
                t.y = acc[im][in][half * 2 + 1] * dv;
                *(float2*)&T[(size_t)r * BN + nbase + in * 8 + 2 * tig] = t;
            }
        }
    }
}

__global__ void __launch_bounds__(256)
k_gemm1(const float* __restrict__ x, const float* __restrict__ W1) {
    gemm_tc_body<128, 128, 2, 4, false>(x, W1, nullptr, g_t1);
}

__global__ void __launch_bounds__(256)
k_gemm2(const float* __restrict__ W2, const float* __restrict__ b1) {
    gemm_tc_body<128, 64, 2, 4, true>(g_agg1, W2, b1, g_t2);
}

// ---------------- layer-1 aggregate: gather, warp per node, MLP=2 -----------
__global__ void k_agg1() {
    int n    = (blockIdx.x * blockDim.x + threadIdx.x) >> 5;
    int lane = threadIdx.x & 31;
    if (n >= N_NODES) return;

    int   s0 = g_rowstart[n];
    int   s1 = g_rowstart[n + 1];
    float dv = g_dinv[n];

    float4 acc = *(const float4*)&g_t1[(size_t)n * D_H1 + lane * 4];

    int e = s0;
    for (; e + 1 < s1; e += 2) {
        int srcA = g_csr_src[e];
        int srcB = g_csr_src[e + 1];
        float4 vA = *(const float4*)&g_t1[(size_t)srcA * D_H1 + lane * 4];
        float4 vB = *(const float4*)&g_t1[(size_t)srcB * D_H1 + lane * 4];
        acc.x += vA.x + vB.x;
        acc.y += vA.y + vB.y;
        acc.z += vA.z + vB.z;
        acc.w += vA.w + vB.w;
    }
    if (e < s1) {
        int src = g_csr_src[e];
        float4 v = *(const float4*)&g_t1[(size_t)src * D_H1 + lane * 4];
        acc.x += v.x; acc.y += v.y; acc.z += v.z; acc.w += v.w;
    }
    acc.x *= dv; acc.y *= dv; acc.z *= dv; acc.w *= dv;
    *(float4*)&g_agg1[(size_t)n * D_H1 + lane * 4] = acc;
}

// ---------------- layer-2 aggregate fused with final GEMV, MLP=2 ------------
__global__ void k_agg2_final(const float* __restrict__ b2,
                             const float* __restrict__ W3,
                             const float* __restrict__ b3,
                             float* __restrict__ out)
{
    int n    = (blockIdx.x * blockDim.x + threadIdx.x) >> 5;
    int lane = threadIdx.x & 31;
    if (n >= N_NODES) return;

    int   s0 = g_rowstart[n];
    int   s1 = g_rowstart[n + 1];
    float dv = g_dinv[n];

    float2 acc = *(const float2*)&g_t2[(size_t)n * D_H2 + lane * 2];

    int e = s0;
    for (; e + 1 < s1; e += 2) {
        int srcA = g_csr_src[e];
        int srcB = g_csr_src[e + 1];
        float2 vA = *(const float2*)&g_t2[(size_t)srcA * D_H2 + lane * 2];
        float2 vB = *(const float2*)&g_t2[(size_t)srcB * D_H2 + lane * 2];
        acc.x += vA.x + vB.x;
        acc.y += vA.y + vB.y;
    }
    if (e < s1) {
        int src = g_csr_src[e];
        float2 v = *(const float2*)&g_t2[(size_t)src * D_H2 + lane * 2];
        acc.x += v.x; acc.y += v.y;
    }
    acc.x *= dv; acc.y *= dv;

    float2 bb = *(const float2*)&b2[lane * 2];
    float2 w  = *(const float2*)&W3[lane * 2];
    float h0 = fmaxf(acc.x + bb.x, 0.f);
    float h1 = fmaxf(acc.y + bb.y, 0.f);
    float s  = fmaf(h0, w.x, h1 * w.y);
#pragma unroll
    for (int o = 16; o; o >>= 1) s += __shfl_xor_sync(0xffffffffu, s, o);
    if (lane == 0) out[n] = s + b3[0];
}

// ---------------- launch (single stream; gemm1 at profiled slot #4) ---------
extern "C" void kernel_launch(void* const* d_in, const int* in_sizes, int n_in,
                              void* d_out, int out_size)
{
    const float* x  = (const float*)d_in[0];
    const int*   ei = (const int*)d_in[1];     // int32 edge_index
    const float* W1 = (const float*)d_in[2];
    const float* b1 = (const float*)d_in[3];
    const float* W2 = (const float*)d_in[4];
    const float* b2 = (const float*)d_in[5];
    const float* W3 = (const float*)d_in[6];
    const float* b3 = (const float*)d_in[7];
    float*       out = (float*)d_out;
    (void)in_sizes; (void)n_in; (void)out_size;

    k_count_deg<<<(N_EDGES + 255) / 256, 256>>>(ei);
    k_scan     <<<1, 1024>>>();
    k_fill     <<<(N_EDGES + 255) / 256, 256>>>(ei);

    k_gemm1<<<(N_NODES + 127) / 128, 256>>>(x, W1);        // slot #4
    k_agg1 <<<(N_NODES * 32 + 255) / 256, 256>>>();

    k_gemm2<<<(N_NODES + 127) / 128, 256>>>(W2, b1);
    k_agg2_final<<<(N_NODES * 32 + 255) / 256, 256>>>(b2, W3, b3, out);
}